// round 17
// baseline (speedup 1.0000x reference)
#include <cuda_runtime.h>
#include <cuda_fp16.h>
#include <cstdint>

#define N_NODES 4096
#define N_EDGES 65536
#define LDIM 64
#define KDIM 256
#define EDIM 6
#define KL (KDIM*LDIM)   /* 16384 */
#define MAXDEG 128

// Layout notes: identical to R15/R16 (g_h warp-tile-permuted; g_P in
// mma-B-fragment order with sigma baked into W3pT).

// ---------------- scratch ----------------
__device__ __half g_W3pT[(size_t)KL*LDIM];
__device__ __half g_W2T[KDIM*KDIM];
__device__ __half g_xh[N_NODES*LDIM];
__device__ __half g_h [(size_t)N_EDGES*KDIM];
__device__ __half g_P [(size_t)N_NODES*KL];
__device__ float  g_x1 [N_NODES*LDIM];
__device__ float  g_xb3[N_NODES*LDIM];
__device__ float  g_agg [N_NODES*LDIM];
__device__ float  g_agg2[N_NODES*LDIM];
__device__ int    g_deg[N_NODES];
__device__ int    g_csr[N_NODES*MAXDEG];

// ---------------- helpers ----------------
__device__ __forceinline__ float gelu_f(float x){
    return 0.5f * x * (1.0f + erff(x * 0.70710678118654752440f));
}
__device__ __forceinline__ void mma16(float* c, const uint32_t* a, const uint32_t* b){
    asm volatile(
        "mma.sync.aligned.m16n8k16.row.col.f32.f16.f16.f32 "
        "{%0,%1,%2,%3}, {%4,%5,%6,%7}, {%8,%9}, {%0,%1,%2,%3};\n"
        : "+f"(c[0]), "+f"(c[1]), "+f"(c[2]), "+f"(c[3])
        : "r"(a[0]), "r"(a[1]), "r"(a[2]), "r"(a[3]), "r"(b[0]), "r"(b[1]));
}
__device__ __forceinline__ uint32_t smaddr(const void* p){
    return (uint32_t)__cvta_generic_to_shared(p);
}
__device__ __forceinline__ void ldsm_x4(uint32_t* r, uint32_t a){
    asm volatile("ldmatrix.sync.aligned.m8n8.x4.shared.b16 {%0,%1,%2,%3}, [%4];"
        : "=r"(r[0]), "=r"(r[1]), "=r"(r[2]), "=r"(r[3]) : "r"(a));
}
__device__ __forceinline__ void cp16(void* smem_dst, const void* gsrc){
    asm volatile("cp.async.cg.shared.global [%0], [%1], 16;\n"
                 :: "r"(smaddr(smem_dst)), "l"(gsrc));
}
__device__ __forceinline__ void cp_commit(){
    asm volatile("cp.async.commit_group;\n");
}
template<int N> __device__ __forceinline__ void cp_wait(){
    asm volatile("cp.async.wait_group %0;\n" :: "n"(N));
}
__device__ __forceinline__ int sigma32(int v){
    return (((v & 7) >> 1) << 3) + ((v >> 3) << 1) + (v & 1);
}
__device__ __forceinline__ void red2(float* gptr, float v0, float v1){
    asm volatile("red.global.add.v2.f32 [%0], {%1, %2};"
                 :: "l"(gptr), "f"(v0), "f"(v1) : "memory");
}

// ---------------- prep: W3pT (fragment+sigma order), W2T, xh, deg=0 ----------------
__global__ void k_prep(const float* __restrict__ W3, const float* __restrict__ W2,
                       const float* __restrict__ nodes){
    int idx = blockIdx.x*256 + threadIdx.x;        // 0 .. 1048575
    {
        int col = idx >> 6, i = idx & 63;
        int a = (col & ~31) | sigma32(col & 31);
        int og   = a >> 11;
        int rem  = a & 2047;
        int p    = rem >> 8;
        int rem2 = rem & 255;
        int lane = rem2 >> 3;
        int pos  = rem2 & 7;
        int no = lane >> 2, j = lane & 3;
        int w2 = pos >> 2,  pb = pos & 3;
        int kp   = ((pb >> 1) << 3) + (j << 1) + (pb & 1);
        int slot = ((p << 1) + w2) * 16 + kp;
        int k_log = (slot & ~31) | sigma32(slot & 31);
        int o = (og << 3) + no;
        g_W3pT[idx] = __float2half_rn(W3[k_log*(LDIM*LDIM) + i*LDIM + o]);
    }
    if (idx < KDIM*KDIM){
        int n = idx >> 8, k = idx & 255;
        g_W2T[idx] = __float2half_rn(W2[k*KDIM + n]);
    }
    if (idx < N_NODES*LDIM){
        g_xh[idx] = __float2half_rn(nodes[idx]);
    }
    if (idx < N_NODES) g_deg[idx] = 0;
}

// ---------------- shared GEMM bodies ----------------
#define BMt 128
#define BNt 128
#define PAST 72
#define HAST 40
#define HBKT 32
#define MEGA_SMEM (2*BMt*PAST*2)

__device__ __forceinline__ void gemmP_body(char* smb, int bx, int by,
    const __half* __restrict__ A, __half* __restrict__ C, int tid)
{
    __half* As = (__half*)smb;
    __half* Bs = (__half*)(smb + BMt*PAST*2);
    const int N = KL, K = LDIM;
    int lane = tid & 31, warp = tid >> 5;
    int g = lane >> 2, tg = lane & 3;
    int wm = (warp >> 2) * 64;
    int wn = (warp & 3) * 32;
    size_t bm0 = (size_t)by * BMt;
    size_t bn0 = (size_t)bx * BNt;

    #pragma unroll
    for (int i = tid; i < BMt*8; i += 256){
        int r = i >> 3, s = (i & 7) << 3;
        cp16(&As[r*PAST + s], A + (bm0 + r)*K + s);
    }
    #pragma unroll
    for (int i = tid; i < BNt*8; i += 256){
        int r = i >> 3, s = (i & 7) << 3;
        cp16(&Bs[r*PAST + s], g_W3pT + (size_t)(bn0 + r)*K + s);
    }
    cp_commit();

    float acc[4][4][4];
    #pragma unroll
    for (int a=0;a<4;a++)
        #pragma unroll
        for (int b=0;b<4;b++)
            #pragma unroll
            for (int c=0;c<4;c++) acc[a][b][c] = 0.f;

    int ra = (lane & 7) + ((lane >> 3) & 1) * 8;
    int ca = ((lane >> 4) & 1) * 8;
    int rb = (lane & 7) + ((lane >> 4) & 1) * 8;
    int cb = ((lane >> 3) & 1) * 8;

    cp_wait<0>();
    __syncthreads();

    #pragma unroll
    for (int kk = 0; kk < K; kk += 16){
        uint32_t af[4][4], bf[4][2];
        #pragma unroll
        for (int mi=0; mi<4; mi++)
            ldsm_x4(af[mi], smaddr(&As[(wm + mi*16 + ra)*PAST + kk + ca]));
        #pragma unroll
        for (int p=0; p<2; p++){
            uint32_t r4[4];
            ldsm_x4(r4, smaddr(&Bs[(wn + p*16 + rb)*PAST + kk + cb]));
            bf[2*p  ][0] = r4[0]; bf[2*p  ][1] = r4[1];
            bf[2*p+1][0] = r4[2]; bf[2*p+1][1] = r4[3];
        }
        #pragma unroll
        for (int mi=0; mi<4; mi++)
            #pragma unroll
            for (int ni=0; ni<4; ni++)
                mma16(acc[mi][ni], af[mi], bf[ni]);
    }

    size_t cbase = bn0 + wn + tg*8;
    #pragma unroll
    for (int mi=0; mi<4; mi++){
        size_t r0 = bm0 + wm + mi*16 + g;
        uint4 v0, v1;
        __half2* p0 = (__half2*)&v0;
        __half2* p1 = (__half2*)&v1;
        #pragma unroll
        for (int ni=0; ni<4; ni++){
            p0[ni] = __floats2half2_rn(acc[mi][ni][0], acc[mi][ni][1]);
            p1[ni] = __floats2half2_rn(acc[mi][ni][2], acc[mi][ni][3]);
        }
        *(uint4*)(C + r0*N + cbase)     = v0;
        *(uint4*)(C + (r0+8)*N + cbase) = v1;
    }
}

__device__ __forceinline__ void hgemm_body(char* smb, int bx, int by,
    const float* __restrict__ ea, const float* __restrict__ W1,
    const float* __restrict__ b1, const float* __restrict__ b2, int tid)
{
    __half* As  = (__half*)smb;
    __half* Bs  = (__half*)(smb + 10240);
    float*  eas = (float*)(smb + 20480);
    float*  W1s = (float*)(smb + 23552);
    float*  b1s = (float*)(smb + 29696);

    int lane = tid & 31, warp = tid >> 5;
    int g = lane >> 2, tg = lane & 3;
    int wm = (warp >> 2) * 64;
    int wn = (warp & 3) * 32;
    size_t bm0 = (size_t)by * BMt;
    size_t bn0 = (size_t)bx * BNt;

    for (int i = tid; i < BMt*EDIM; i += 256) eas[i] = ea[bm0*EDIM + i];
    for (int i = tid; i < EDIM*KDIM; i += 256) W1s[i] = W1[i];
    if (tid < KDIM) b1s[tid] = b1[tid];

    float acc[4][4][4];
    #pragma unroll
    for (int a=0;a<4;a++)
        #pragma unroll
        for (int b=0;b<4;b++)
            #pragma unroll
            for (int c=0;c<4;c++) acc[a][b][c] = 0.f;

    int ra = (lane & 7) + ((lane >> 3) & 1) * 8;
    int ca = ((lane >> 4) & 1) * 8;
    int rb = (lane & 7) + ((lane >> 4) & 1) * 8;
    int cb = ((lane >> 3) & 1) * 8;

    __syncthreads();

    for (int k0 = 0; k0 < KDIM; k0 += HBKT){
        #pragma unroll
        for (int i = tid; i < BMt*4; i += 256){
            int r = i >> 2, s = (i & 3) << 3;
            cp16(&Bs[r*HAST + s], g_W2T + (size_t)(bn0 + r)*KDIM + k0 + s);
        }
        cp_commit();
        {
            int c = tid & 31;
            int rg = tid >> 5;
            float w0 = W1s[0*KDIM + k0 + c], w1 = W1s[1*KDIM + k0 + c];
            float w2 = W1s[2*KDIM + k0 + c], w3 = W1s[3*KDIM + k0 + c];
            float w4 = W1s[4*KDIM + k0 + c], w5 = W1s[5*KDIM + k0 + c];
            float bb = b1s[k0 + c];
            #pragma unroll
            for (int i = 0; i < 16; i++){
                int r = rg*16 + i;
                const float* er = &eas[r*EDIM];
                float v = bb + er[0]*w0 + er[1]*w1 + er[2]*w2 + er[3]*w3 + er[4]*w4 + er[5]*w5;
                As[r*HAST + c] = __float2half_rn(gelu_f(v));
            }
        }
        cp_wait<0>();
        __syncthreads();
        #pragma unroll
        for (int kk = 0; kk < HBKT; kk += 16){
            uint32_t af[4][4], bf[4][2];
            #pragma unroll
            for (int mi=0; mi<4; mi++)
                ldsm_x4(af[mi], smaddr(&As[(wm + mi*16 + ra)*HAST + kk + ca]));
            #pragma unroll
            for (int p=0; p<2; p++){
                uint32_t r4[4];
                ldsm_x4(r4, smaddr(&Bs[(wn + p*16 + rb)*HAST + kk + cb]));
                bf[2*p  ][0] = r4[0]; bf[2*p  ][1] = r4[1];
                bf[2*p+1][0] = r4[2]; bf[2*p+1][1] = r4[3];
            }
            #pragma unroll
            for (int mi=0; mi<4; mi++)
                #pragma unroll
                for (int ni=0; ni<4; ni++)
                    mma16(acc[mi][ni], af[mi], bf[ni]);
        }
        __syncthreads();
    }

    size_t cbase = bn0 + wn + tg*8;
    #pragma unroll
    for (int mi=0; mi<4; mi++){
        size_t r0 = bm0 + wm + mi*16 + g;
        uint4 v0, v1;
        __half2* p0 = (__half2*)&v0;
        __half2* p1 = (__half2*)&v1;
        #pragma unroll
        for (int ni=0; ni<4; ni++){
            int cg = (int)bn0 + wn + ni*8 + (tg<<1);
            float bb0 = b2[cg], bb1 = b2[cg+1];
            p0[ni] = __floats2half2_rn(gelu_f(acc[mi][ni][0] + bb0), gelu_f(acc[mi][ni][1] + bb1));
            p1[ni] = __floats2half2_rn(gelu_f(acc[mi][ni][2] + bb0), gelu_f(acc[mi][ni][3] + bb1));
        }
        *(uint4*)(g_h + r0*KDIM + cbase)     = v0;
        *(uint4*)(g_h + (r0+8)*KDIM + cbase) = v1;
    }
}

// ---------------- mega1: hgemm(+bucket) U agg/xb3-init U gemmP(conv1) ----------------
__global__ __launch_bounds__(256, 2) void k_mega1(
    const float* __restrict__ ea, const float* __restrict__ W1,
    const float* __restrict__ b1, const float* __restrict__ b2,
    const int* __restrict__ ei,
    const __half* __restrict__ A, __half* __restrict__ C,
    const float* __restrict__ nodes, const float* __restrict__ b3)
{
    __shared__ __align__(16) char smb[MEGA_SMEM];
    int bid = blockIdx.x;
    int tid = threadIdx.x;

    if (bid < 1024){
        int gtid = bid*256 + tid;
        if (gtid < N_EDGES){
            int s = ei[gtid];
            int slot = atomicAdd(&g_deg[s], 1);
            g_csr[s*MAXDEG + slot] = gtid;
        }
        hgemm_body(smb, bid & 1, bid >> 1, ea, W1, b1, b2, tid);
    } else if (bid < 1280){
        // xb3 init: 256 blocks x 256 threads = 65536 = 4096 nodes x 16 col-quads
        int idx = (bid - 1024)*256 + tid;
        int n = idx >> 4, oq = idx & 15;
        const float* xr = nodes + (size_t)n*LDIM;
        const float4* B4 = (const float4*)b3;
        float4 acc = make_float4(0.f, 0.f, 0.f, 0.f);
        #pragma unroll 8
        for (int i = 0; i < LDIM; i++){
            float xv = __ldg(&xr[i]);
            float4 w = __ldg(&B4[i*16 + oq]);
            acc.x += xv*w.x; acc.y += xv*w.y; acc.z += xv*w.z; acc.w += xv*w.w;
        }
        ((float4*)(g_xb3 + (size_t)n*LDIM))[oq] = acc;
    } else if (bid < 1792){
        // agg/agg2 zero: 512 blocks x 256 threads x float2 = 262144 floats each
        int idx = (bid - 1280)*256 + tid;
        ((float2*)g_agg )[idx] = make_float2(0.f, 0.f);
        ((float2*)g_agg2)[idx] = make_float2(0.f, 0.f);
    } else if (bid < 2048){
        // idle filler (keeps gemmP range aligned)
    } else {
        int r = bid - 2048;
        gemmP_body(smb, r & 127, r >> 7, A, C, tid);
    }
}

// ---------------- standalone gemmP (conv 2) ----------------
__global__ __launch_bounds__(256, 3) void k_gemmP(
    const __half* __restrict__ A, __half* __restrict__ C)
{
    __shared__ __align__(16) char smb[MEGA_SMEM];
    gemmP_body(smb, blockIdx.x, blockIdx.y, A, C, threadIdx.x);
}

// ---------------- fp16 edge stage: no earr stage, warp-uniform h gather, v2 red ----------------
#define HST 264

__global__ __launch_bounds__(256) void k_edge(const int* __restrict__ ei,
                                              float* __restrict__ agg)
{
    __shared__ __half hs[16*HST];
    __shared__ float xb3s[LDIM];

    int n = blockIdx.x;
    int deg = g_deg[n];
    if (deg == 0) return;

    int t = threadIdx.x;
    int lane = t & 31, warp = t >> 5;
    int g = lane >> 2, tg = lane & 3;
    int n0 = warp * 8;

    // B fragments direct from gmem (8 x LDG.128 per lane, stays in regs)
    uint4 pf[8];
    {
        const uint4* Pf = (const uint4*)(g_P + (size_t)n * KL + (warp << 11)) + lane;
        #pragma unroll
        for (int p = 0; p < 8; p++) pf[p] = Pf[p << 5];
    }
    if (t < LDIM) xb3s[t] = g_xb3[n*LDIM + t];

    int ra = (lane & 7) + ((lane >> 3) & 1) * 8;
    int ca = ((lane >> 4) & 1) * 8;

    const int* __restrict__ csr = g_csr + n*MAXDEG;
    int nch = (deg + 15) >> 4;

    for (int c = 0; c < nch; c++){
        int base = c*16;
        // warp-uniform h gather: warp w stages rows w and w+8 (512B each, coalesced)
        int s0 = base + warp;     if (s0 >= deg) s0 = deg - 1;
        int s1 = base + warp + 8; if (s1 >= deg) s1 = deg - 1;
        int e0 = __ldg(&csr[s0]);
        int e1 = __ldg(&csr[s1]);
        cp16(&hs[ warp   *HST + lane*8], g_h + (size_t)e0*KDIM + lane*8);
        cp16(&hs[(warp+8)*HST + lane*8], g_h + (size_t)e1*KDIM + lane*8);
        cp_commit();
        cp_wait<0>();
        __syncthreads();

        int csz = min(16, deg - base);
        float acc[4] = {0,0,0,0};
        #pragma unroll
        for (int kb = 0; kb < 16; kb++){
            uint32_t a[4];
            ldsm_x4(a, smaddr(&hs[ra*HST + kb*16 + ca]));
            uint32_t b[2];
            const uint32_t* pw = (const uint32_t*)&pf[kb >> 1];
            if (kb & 1){ b[0] = pw[2]; b[1] = pw[3]; }
            else       { b[0] = pw[0]; b[1] = pw[1]; }
            mma16(acc, a, b);
        }
        int cc = n0 + (tg<<1);
        float x0 = xb3s[cc], x1 = xb3s[cc+1];
        if (g < csz){
            int d = __ldg(&ei[N_EDGES + __ldg(&csr[base + g])]);
            red2(&agg[(size_t)d*LDIM + cc], acc[0] + x0, acc[1] + x1);
        }
        if (g + 8 < csz){
            int d = __ldg(&ei[N_EDGES + __ldg(&csr[base + g + 8])]);
            red2(&agg[(size_t)d*LDIM + cc], acc[2] + x0, acc[3] + x1);
        }
        __syncthreads();
    }
}

// ---------------- conv boundary: 4 outputs/thread, float4 W ----------------
__global__ __launch_bounds__(256) void k_boundary(
    const float* __restrict__ x, const float* __restrict__ Wr,
    const float* __restrict__ agg, const float* __restrict__ bias,
    const float* __restrict__ b3,
    float* __restrict__ x1, __half* __restrict__ xh, float* __restrict__ xb3)
{
    __shared__ float xs[16*LDIM];
    __shared__ float xs2[16*LDIM];
    int t = threadIdx.x;
    int n0 = blockIdx.x * 16;
    ((float4*)xs)[t] = ((const float4*)(x + (size_t)n0*LDIM))[t];
    __syncthreads();
    int nl = t >> 4, oq = t & 15;
    int n = n0 + nl;
    const float4* W4 = (const float4*)Wr;
    float4 acc = make_float4(0.f, 0.f, 0.f, 0.f);
    #pragma unroll 8
    for (int i = 0; i < LDIM; i++){
        float xv = xs[nl*LDIM + i];
        float4 w = __ldg(&W4[i*16 + oq]);
        acc.x += xv*w.x; acc.y += xv*w.y; acc.z += xv*w.z; acc.w += xv*w.w;
    }
    float4 ag = ((const float4*)(agg + (size_t)n*LDIM))[oq];
    float4 bs = __ldg(&((const float4*)bias)[oq]);
    acc.x = gelu_f(acc.x + ag.x + bs.x);
    acc.y = gelu_f(acc.y + ag.y + bs.y);
    acc.z = gelu_f(acc.z + ag.z + bs.z);
    acc.w = gelu_f(acc.w + ag.w + bs.w);
    ((float4*)(x1 + (size_t)n*LDIM))[oq] = acc;
    __half2 h0 = __floats2half2_rn(acc.x, acc.y);
    __half2 h1 = __floats2half2_rn(acc.z, acc.w);
    uint2 hp; hp.x = *(uint32_t*)&h0; hp.y = *(uint32_t*)&h1;
    *(uint2*)(xh + (size_t)n*LDIM + oq*4) = hp;
    ((float4*)xs2)[nl*16 + oq] = acc;
    __syncthreads();
    const float4* B4 = (const float4*)b3;
    float4 a2 = make_float4(0.f, 0.f, 0.f, 0.f);
    #pragma unroll 8
    for (int i = 0; i < LDIM; i++){
        float xv = xs2[nl*LDIM + i];
        float4 w = __ldg(&B4[i*16 + oq]);
        a2.x += xv*w.x; a2.y += xv*w.y; a2.z += xv*w.z; a2.w += xv*w.w;
    }
    ((float4*)(xb3 + (size_t)n*LDIM))[oq] = a2;
}

// ---------------- final: 4 outputs/thread ----------------
__global__ __launch_bounds__(256) void k_final(
    const float* __restrict__ x, const float* __restrict__ Wr,
    const float* __restrict__ agg, const float* __restrict__ bias,
    float* __restrict__ out)
{
    __shared__ float xs[16*LDIM];
    int t = threadIdx.x;
    int n0 = blockIdx.x * 16;
    ((float4*)xs)[t] = ((const float4*)(x + (size_t)n0*LDIM))[t];
    __syncthreads();
    int nl = t >> 4, oq = t & 15;
    int n = n0 + nl;
    const float4* W4 = (const float4*)Wr;
    float4 acc = make_float4(0.f, 0.f, 0.f, 0.f);
    #pragma unroll 8
    for (int i = 0; i < LDIM; i++){
        float xv = xs[nl*LDIM + i];
        float4 w = __ldg(&W4[i*16 + oq]);
        acc.x += xv*w.x; acc.y += xv*w.y; acc.z += xv*w.z; acc.w += xv*w.w;
    }
    float4 ag = ((const float4*)(agg + (size_t)n*LDIM))[oq];
    float4 bs = __ldg(&((const float4*)bias)[oq]);
    acc.x += ag.x + bs.x;
    acc.y += ag.y + bs.y;
    acc.z += ag.z + bs.z;
    acc.w += ag.w + bs.w;
    ((float4*)(out + (size_t)n*LDIM))[oq] = acc;
}

// ---------------- launch ----------------
extern "C" void kernel_launch(void* const* d_in, const int* in_sizes, int n_in,
                              void* d_out, int out_size)
{
    const float* nodes = (const float*)d_in[0];
    const int*   ei    = (const int*)  d_in[1];
    const float* ea    = (const float*)d_in[2];
    const float* W1    = (const float*)d_in[3];
    const float* b1    = (const float*)d_in[4];
    const float* W2    = (const float*)d_in[5];
    const float* b2    = (const float*)d_in[6];
    const float* W3    = (const float*)d_in[7];
    const float* b3    = (const float*)d_in[8];
    const float* Wr    = (const float*)d_in[9];
    const float* bias  = (const float*)d_in[10];
    float* out = (float*)d_out;

    __half *pP, *pXh;
    float *pX1, *pXb3, *pAgg, *pAgg2;
    cudaGetSymbolAddress((void**)&pP,    g_P);
    cudaGetSymbolAddress((void**)&pXh,   g_xh);
    cudaGetSymbolAddress((void**)&pX1,   g_x1);
    cudaGetSymbolAddress((void**)&pXb3,  g_xb3);
    cudaGetSymbolAddress((void**)&pAgg,  g_agg);
    cudaGetSymbolAddress((void**)&pAgg2, g_agg2);

    k_prep    <<<(KL*LDIM)/256, 256>>>(W3, W2, nodes);                         // 0
    k_mega1   <<<6144, 256>>>(ea, W1, b1, b2, ei, pXh, pP, nodes, b3);         // 1
    k_edge    <<<N_NODES, 256>>>(ei, pAgg);                                    // 2
    k_boundary<<<N_NODES/16, 256>>>(nodes, Wr, pAgg, bias, b3, pX1, pXh, pXb3);// 3 <- profiled
    k_gemmP   <<<dim3(KL/BNt, N_NODES/BMt), 256>>>(pXh, pP);                   // 4 (conv2 P)
    k_edge    <<<N_NODES, 256>>>(ei, pAgg2);                                   // 5
    k_final   <<<N_NODES/16, 256>>>(pX1, Wr, pAgg2, bias, out);                // 6
}